// round 13
// baseline (speedup 1.0000x reference)
#include <cuda_runtime.h>

// Fixed shapes per reference: B=4096, IN=HID=8192, fp32
#define IN_DIM   8192
#define HID_DIM  8192
#define COL4     (IN_DIM / 4)                    // 2048 float4 per row
#define ROW_GRPS 128                             // colsum row groups
#define ROWS_PER_GRP (HID_DIM / ROW_GRPS)        // 64 rows per block

// Device-global scratch (allocation-free rule: device globals allowed)
__device__ float g_partial[ROW_GRPS * IN_DIM];   // 4 MB
__device__ float g_wsum[IN_DIM];                 // 32 KB

// ---------------- Kernel 1: partial column sums of W [HID, IN] ----------------
// grid = (8, 128), block = 256. 81.6% of spec — frozen.
__global__ __launch_bounds__(256) void colsum_partial(const float* __restrict__ w) {
    const int col4 = blockIdx.x * 256 + threadIdx.x;        // 0..2047
    const int r0   = blockIdx.y * ROWS_PER_GRP;
    const float4* __restrict__ w4 = reinterpret_cast<const float4*>(w);

    float4 acc = make_float4(0.f, 0.f, 0.f, 0.f);
    #pragma unroll 8
    for (int r = 0; r < ROWS_PER_GRP; ++r) {
        float4 v = __ldg(&w4[(size_t)(r0 + r) * COL4 + col4]);
        acc.x += v.x; acc.y += v.y; acc.z += v.z; acc.w += v.w;
    }
    reinterpret_cast<float4*>(g_partial)[(size_t)blockIdx.y * COL4 + col4] = acc;
}

// ---------------- Kernel 2: wide reduce 128 partials -> g_wsum ----------------
// grid = 32, block = 256 (~1 us) — frozen.
__global__ __launch_bounds__(256) void reduce_partial() {
    const int t    = threadIdx.x;
    const int cl   = t & 63;
    const int gq   = t >> 6;
    const int col4 = blockIdx.x * 64 + cl;
    const float4* __restrict__ p4 = reinterpret_cast<const float4*>(g_partial);

    float4 acc = make_float4(0.f, 0.f, 0.f, 0.f);
    #pragma unroll 8
    for (int i = 0; i < 32; ++i) {
        float4 v = p4[(size_t)(gq * 32 + i) * COL4 + col4];
        acc.x += v.x; acc.y += v.y; acc.z += v.z; acc.w += v.w;
    }

    __shared__ float4 s[4][64];
    s[gq][cl] = acc;
    __syncthreads();

    if (t < 64) {
        float4 a = s[0][t], b = s[1][t], c = s[2][t], d = s[3][t];
        float4 r;
        r.x = (a.x + b.x) + (c.x + d.x);
        r.y = (a.y + b.y) + (c.y + d.y);
        r.z = (a.z + b.z) + (c.z + d.z);
        r.w = (a.w + b.w) + (c.w + d.w);
        reinterpret_cast<float4*>(g_wsum)[blockIdx.x * 64 + t] = r;
    }
}

// ---------------- Kernel 3: out[b] = 0.75 * dot(x[b], wsum) ----------------
// R1's proven body, with ONE change: a 46 KB static smem pad caps occupancy
// at 4 CTAs/SM (228/46) to cut cross-CTA L1tex-queue contention
// (oe*MLP_p1: 64 -> 32, predicted spread 2.0 -> ~1.3).
#define SMEM_PAD_FLOATS 11776                    // 47104 B < 48 KB static limit
__global__ __launch_bounds__(256) void rowdot(const float* __restrict__ x,
                                              float* __restrict__ out) {
    __shared__ float s_pad[SMEM_PAD_FLOATS];     // first 8 floats = warp sums

    const int b = blockIdx.x;
    const float4* __restrict__ x4 =
        reinterpret_cast<const float4*>(x + (size_t)b * IN_DIM);
    const float4* __restrict__ w4 = reinterpret_cast<const float4*>(g_wsum);

    float acc = 0.f;
    #pragma unroll
    for (int k = 0; k < COL4 / 256; ++k) {       // 8 LDG.128 on x, MLP=8
        const int i = threadIdx.x + k * 256;
        float4 xv = __ldg(&x4[i]);
        float4 wv = w4[i];
        acc = fmaf(xv.x, wv.x, acc);
        acc = fmaf(xv.y, wv.y, acc);
        acc = fmaf(xv.z, wv.z, acc);
        acc = fmaf(xv.w, wv.w, acc);
    }

    #pragma unroll
    for (int off = 16; off > 0; off >>= 1)
        acc += __shfl_xor_sync(0xFFFFFFFFu, acc, off);

    const int lane = threadIdx.x & 31;
    const int wid  = threadIdx.x >> 5;
    if (lane == 0) s_pad[wid] = acc;
    __syncthreads();

    if (wid == 0) {
        float v = (lane < 8) ? s_pad[lane] : 0.f;
        #pragma unroll
        for (int off = 4; off > 0; off >>= 1)
            v += __shfl_xor_sync(0xFFFFFFFFu, v, off);
        if (lane == 0) out[b] = v * 0.75f;       // (/2) * 1.5
    }
}

extern "C" void kernel_launch(void* const* d_in, const int* in_sizes, int n_in,
                              void* d_out, int out_size) {
    const float* x = (const float*)d_in[0];   // [B, IN]
    const float* w = (const float*)d_in[1];   // [HID, IN]
    float* out = (float*)d_out;               // [B, 1]
    const int B = in_sizes[0] / IN_DIM;

    dim3 g1(COL4 / 256, ROW_GRPS);            // (8, 128)
    colsum_partial<<<g1, 256>>>(w);
    reduce_partial<<<32, 256>>>();
    rowdot<<<B, 256>>>(x, out);
}